// round 15
// baseline (speedup 1.0000x reference)
#include <cuda_runtime.h>
#include <cuda_bf16.h>
#include <cuda_fp16.h>
#include <cstdint>

#define NN 100000
#define RR 3
#define EE 800000
#define F  128
#define NB 98          // scan chunks per relation: ceil(NN/1024)

// ---------------- scratch (device globals: allocation-free rule) ----------
__device__ __half g_tmp3[(size_t)RR * NN * F]; // per-relation GEMM outputs (fp16, ns-scaled)
__device__ __half g_act[(size_t)NN * F];       // layer-1 activations (fp16)
__device__ float  g_ns[RR * NN];               // rsqrt(max(deg_out,1))
__device__ float  g_nd[RR * NN];               // counts, then rsqrt(max(deg_in,1))
__device__ int    g_off[RR * NN];              // CSR offsets (per relation, by dst)
__device__ int    g_degi[RR * NN];             // int in-degree
__device__ int    g_cur[RR * NN];              // absolute bucket cursors
__device__ int    g_csrc[(size_t)RR * EE];     // dst-sorted src indices
__device__ int    g_bsum[RR * NB];             // per-chunk totals -> exclusive prefixes
__device__ int    g_scan_done;                 // tail-block election counter (self-resetting)
__device__ __half g_whf[2][RR][F * F];         // W fp16 planes [k][n]

// ---------------- prep: W fp16 planes + zero norms (merged) ---------------
__global__ void prep_zero_k(const float* __restrict__ W1, const float* __restrict__ W2) {
    int i = blockIdx.x * blockDim.x + threadIdx.x;
    if (i < 2 * RR * F * F) {
        int layer = i / (RR * F * F);
        int rem   = i % (RR * F * F);
        ((__half*)g_whf[layer])[rem] = __float2half_rn((layer ? W2 : W1)[rem]);
    }
    if (i < RR * NN) { g_ns[i] = 0.f; g_nd[i] = 0.f; }
}

// ---------------- degree count (2D grid: y = relation) --------------------
__global__ void degree_k(const int* __restrict__ src, const int* __restrict__ dst) {
    int e = blockIdx.x * blockDim.x + threadIdx.x;
    int r = blockIdx.y;
    if (e < EE) {
        atomicAdd(&g_ns[r * NN + src[r * EE + e]], 1.0f);
        atomicAdd(&g_nd[r * NN + dst[r * EE + e]], 1.0f);
    }
}

// ---------------- src-norm finalize (all the GEMM needs) ------------------
__global__ void ns_fin_k() {
    int i = blockIdx.x * blockDim.x + threadIdx.x;
    if (i < RR * NN) g_ns[i] = rsqrtf(fmaxf(g_ns[i], 1.0f));
}

// ---- scan phase 1 + fused tail-block phase 2 -----------------------------
__global__ void scan_part_k() {
    int r   = blockIdx.y;
    int idx = blockIdx.x * 1024 + threadIdx.x;
    int lane = threadIdx.x & 31, wid = threadIdx.x >> 5;

    int v = 0;
    if (idx < NN) v = (int)g_nd[r * NN + idx];

    int x = v;
#pragma unroll
    for (int o = 1; o < 32; o <<= 1) {
        int y = __shfl_up_sync(0xFFFFFFFFu, x, o);
        if (lane >= o) x += y;
    }
    __shared__ int wsum[32];
    __shared__ int sh_last;
    if (lane == 31) wsum[wid] = x;
    __syncthreads();
    if (wid == 0) {
        int w = wsum[lane];
#pragma unroll
        for (int o = 1; o < 32; o <<= 1) {
            int y = __shfl_up_sync(0xFFFFFFFFu, w, o);
            if (lane >= o) w += y;
        }
        wsum[lane] = w;
    }
    __syncthreads();

    int excl = x - v + (wid ? wsum[wid - 1] : 0);
    if (idx < NN) {
        g_off[r * NN + idx]  = excl;
        g_degi[r * NN + idx] = v;
    }
    if (threadIdx.x == 0) {
        g_bsum[r * NB + blockIdx.x] = wsum[31];
        __threadfence();
        int done = atomicAdd(&g_scan_done, 1);
        sh_last = (done == NB * RR - 1);
    }
    __syncthreads();

    if (sh_last) {
        __shared__ int sh[RR * 128];
        int t = threadIdx.x;
        int rr = t >> 7, j = t & 127;
        int bv = 0;
        if (t < RR * 128) {
            bv = (j < NB) ? g_bsum[rr * NB + j] : 0;
            sh[t] = bv;
        }
        __syncthreads();
#pragma unroll
        for (int o = 1; o < 128; o <<= 1) {
            int y = 0;
            if (t < RR * 128 && j >= o) y = sh[rr * 128 + j - o];
            __syncthreads();
            if (t < RR * 128) sh[t] += y;
            __syncthreads();
        }
        if (t < RR * 128 && j < NB) g_bsum[rr * NB + j] = sh[t] - bv;
        if (t == 0) g_scan_done = 0;
    }
}

// ---- dst-norm finalize + apply chunk prefix + cursors --------------------
__global__ void nd_fin_k() {
    int i = blockIdx.x * blockDim.x + threadIdx.x;
    if (i < RR * NN) {
        int r = i / NN, idx = i - r * NN;
        int off = g_off[i] + g_bsum[r * NB + (idx >> 10)];
        g_off[i] = off;
        g_cur[i] = off;
        g_nd[i] = rsqrtf(fmaxf(g_nd[i], 1.0f));
    }
}

__global__ void fill_csr_k(const int* __restrict__ src, const int* __restrict__ dst) {
    int e = blockIdx.x * blockDim.x + threadIdx.x;
    int r = blockIdx.y;
    if (e < EE) {
        int pos = atomicAdd(&g_cur[r * NN + dst[r * EE + e]], 1);
        g_csrc[(size_t)r * EE + pos] = src[r * EE + e];
    }
}

// ---------------- streamed-B fp16 tensor-core GEMM ------------------------
// g_tmp3[r] = (X @ W[r]) * ns_r[row]  (fp16 store)
// A (64x128 fp16) smem-resident (fp32 or fp16 source); B streamed as
// 64-k-row chunks, cp.async double-buffered.  52.2 KB smem -> 4 CTAs/SM.
#define BM   64
#define PA   136
#define APLANE (BM * PA)      // elems of A plane
#define B64    (64 * PA)      // elems per B chunk
#define NCHUNK (RR * 2)       // 6 chunks of 64 k-rows
#define GEMM_SMEM ((APLANE + 2 * B64) * 2)   // 52224 bytes

#define MMA_F16(d, a, b) \
    asm volatile("mma.sync.aligned.m16n8k16.row.col.f32.f16.f16.f32 " \
                 "{%0,%1,%2,%3}, {%4,%5,%6,%7}, {%8,%9}, {%0,%1,%2,%3};" \
                 : "+f"((d)[0]), "+f"((d)[1]), "+f"((d)[2]), "+f"((d)[3]) \
                 : "r"((a)[0]), "r"((a)[1]), "r"((a)[2]), "r"((a)[3]), \
                   "r"((b)[0]), "r"((b)[1]))

#define LDSM_X4(r, addr) \
    asm volatile("ldmatrix.sync.aligned.m8n8.x4.shared.b16 {%0,%1,%2,%3}, [%4];" \
                 : "=r"((r)[0]), "=r"((r)[1]), "=r"((r)[2]), "=r"((r)[3]) \
                 : "r"(addr))

#define LDSM_X4_T(r, addr) \
    asm volatile("ldmatrix.sync.aligned.m8n8.x4.trans.shared.b16 {%0,%1,%2,%3}, [%4];" \
                 : "=r"((r)[0]), "=r"((r)[1]), "=r"((r)[2]), "=r"((r)[3]) \
                 : "r"(addr))

__device__ __forceinline__ void cp_async16(uint32_t dst, const void* src) {
    asm volatile("cp.async.cg.shared.global [%0], [%1], 16;" :: "r"(dst), "l"(src));
}
#define CP_COMMIT() asm volatile("cp.async.commit_group;" ::: "memory")
#define CP_WAIT1()  asm volatile("cp.async.wait_group 1;" ::: "memory")
#define CP_WAIT0()  asm volatile("cp.async.wait_group 0;" ::: "memory")

__global__ void __launch_bounds__(256, 4)
gemm3_k(const float* __restrict__ Xf, const __half* __restrict__ Xh,
        int layer, __half* __restrict__ outp) {
    extern __shared__ __align__(16) __half sh[];
    __half* Ah = sh;                             // [64][PA]

    int t = threadIdx.x;
    int row0 = blockIdx.x * BM;

    uint32_t sbase = (uint32_t)__cvta_generic_to_shared(sh);
    uint32_t sbB   = sbase + APLANE * 2;         // byte addr of buf0 B

    // ---- prefetch chunk 0 of B while filling A (64x128 fp16 = 4 cp/thread)
    {
        const __half* hs = g_whf[layer][0];
#pragma unroll
        for (int i = 0; i < 4; i++) {
            int f = t + 256 * i;                 // 0..1023
            int k = f >> 4, n8 = (f & 15) << 3;
            cp_async16(sbB + (uint32_t)(k * PA + n8) * 2, hs + k * F + n8);
        }
        CP_COMMIT();
    }

    // ---- fill A: [m=64][k=128] fp16 (from fp32 x or fp16 act) ----
    if (Xh == nullptr) {
#pragma unroll
        for (int i = 0; i < 8; i++) {
            int f   = t + 256 * i;
            int row = f >> 5;
            int c4  = (f & 31) << 2;
            int grow = row0 + row;
            float4 v = make_float4(0.f, 0.f, 0.f, 0.f);
            if (grow < NN) v = *reinterpret_cast<const float4*>(Xf + (size_t)grow * F + c4);
            int base = row * PA + c4;
            *reinterpret_cast<__half2*>(&Ah[base])     = __floats2half2_rn(v.x, v.y);
            *reinterpret_cast<__half2*>(&Ah[base + 2]) = __floats2half2_rn(v.z, v.w);
        }
    } else {
#pragma unroll
        for (int i = 0; i < 8; i++) {
            int f   = t + 256 * i;
            int row = f >> 5;
            int c4  = (f & 31) << 2;
            int grow = row0 + row;
            uint2 v = make_uint2(0u, 0u);
            if (grow < NN) v = *reinterpret_cast<const uint2*>(Xh + (size_t)grow * F + c4);
            *reinterpret_cast<uint2*>(&Ah[row * PA + c4]) = v;
        }
    }

    int lane = t & 31, warp = t >> 5;
    int mbase = (warp & 1) * 32;    // 2 m-groups of 32 rows
    int nbase = (warp >> 1) * 32;   // 4 n-groups of 32 cols

    int lrow = lane & 7;
    int m8   = ((lane >> 3) & 1) << 3;
    int k8   = ((lane >> 4) & 1) << 3;

    unsigned aA0 = sbase + (unsigned)(((mbase + lrow + m8) * PA + k8) * 2);
    unsigned aA1 = aA0 + 16 * PA * 2;
    unsigned bwoff = (unsigned)(((lrow + m8) * PA + nbase + k8) * 2);

    int grp = lane >> 2;
    int cof = (lane & 3) * 2;

    for (int r = 0; r < RR; r++) {
        float acc[2][4][4];
#pragma unroll
        for (int mt = 0; mt < 2; mt++)
#pragma unroll
            for (int nt = 0; nt < 4; nt++)
#pragma unroll
                for (int c = 0; c < 4; c++) acc[mt][nt][c] = 0.f;

#pragma unroll
        for (int ch = 0; ch < 2; ch++) {
            int c = r * 2 + ch;
            __syncthreads();   // prior reads of buf[(c+1)&1] done (A fill on c=0)
            if (c + 1 < NCHUNK) {
                int cn = c + 1;
                const __half* hs = g_whf[layer][cn >> 1] + (cn & 1) * 64 * F;
                uint32_t bb = sbB + (uint32_t)(cn & 1) * (B64 * 2);
#pragma unroll
                for (int i = 0; i < 4; i++) {
                    int f = t + 256 * i;
                    int k = f >> 4, n8 = (f & 15) << 3;
                    cp_async16(bb + (uint32_t)(k * PA + n8) * 2, hs + k * F + n8);
                }
                CP_COMMIT();
                CP_WAIT1();
            } else {
                CP_WAIT0();
            }
            __syncthreads();   // chunk c visible to all warps

            uint32_t bufb = sbB + (uint32_t)(c & 1) * (B64 * 2) + bwoff;
#pragma unroll
            for (int kci = 0; kci < 4; kci++) {
                int gk = ch * 4 + kci;
                unsigned aOff = gk * 32;
                unsigned bB = bufb + kci * 16 * PA * 2;

                unsigned ah[2][4];
                LDSM_X4(ah[0], aA0 + aOff);
                LDSM_X4(ah[1], aA1 + aOff);

#pragma unroll
                for (int np = 0; np < 2; np++) {
                    unsigned bh[4];
                    LDSM_X4_T(bh, bB + np * 16 * 2);
                    unsigned* bh0 = bh;
                    unsigned* bh1 = bh + 2;
#pragma unroll
                    for (int mt = 0; mt < 2; mt++) {
                        MMA_F16(acc[mt][2 * np],     ah[mt], bh0);
                        MMA_F16(acc[mt][2 * np + 1], ah[mt], bh1);
                    }
                }
            }
        }

        // ---- epilogue: scale by norm_src[row], store fp16 ----
        const float* nsr = g_ns + r * NN;
        __half* op = outp + (size_t)r * NN * F;
#pragma unroll
        for (int mt = 0; mt < 2; mt++) {
            int rA = row0 + mbase + mt * 16 + grp;
            int rB = rA + 8;
            float sA = (rA < NN) ? nsr[rA] : 0.f;
            float sB = (rB < NN) ? nsr[rB] : 0.f;
#pragma unroll
            for (int nt = 0; nt < 4; nt++) {
                int col = nbase + nt * 8 + cof;
                if (rA < NN)
                    *reinterpret_cast<__half2*>(op + (size_t)rA * F + col) =
                        __floats2half2_rn(acc[mt][nt][0] * sA, acc[mt][nt][1] * sA);
                if (rB < NN)
                    *reinterpret_cast<__half2*>(op + (size_t)rB * F + col) =
                        __floats2half2_rn(acc[mt][nt][2] * sB, acc[mt][nt][3] * sB);
            }
        }
    }
}

// ---------------- fused aggregation: dual-edge warp per node --------------
// Two 16-lane halves of the warp each cover the full 128-col row (uint4 = 8
// halves/lane); half h processes edges j+h, j+h+2, ... of the SAME node.
// Cross-half reduce once at the end via shfl_xor(16).
__global__ void __launch_bounds__(256)
agg_all_k(const __half* __restrict__ tmp3, const float* __restrict__ bias,
          __half* __restrict__ out_h, float* __restrict__ out_f, int relu) {
    int warp = (blockIdx.x * blockDim.x + threadIdx.x) >> 5;
    int lane = threadIdx.x & 31;
    if (warp >= NN) return;
    int node = warp;
    int half = lane >> 4;          // 0 or 1
    int hl   = lane & 15;
    int c8   = hl * 8;             // 8 half-columns per lane

    int off0 = g_off[node],  off1 = g_off[NN + node],  off2 = g_off[2 * NN + node];
    int cnt0 = g_degi[node], cnt1 = g_degi[NN + node], cnt2 = g_degi[2 * NN + node];
    float nd0 = g_nd[node],  nd1 = g_nd[NN + node],    nd2 = g_nd[2 * NN + node];
    int offs[RR]  = {off0, off1, off2};
    int cnts[RR]  = {cnt0, cnt1, cnt2};
    float nds[RR] = {nd0, nd1, nd2};

    float acc[8];
#pragma unroll
    for (int q = 0; q < 8; q++) acc[q] = 0.f;

#pragma unroll
    for (int r = 0; r < RR; r++) {
        int cnt = cnts[r];
        const int* lst = g_csrc + (size_t)r * EE + offs[r];
        const __half* tmp = tmp3 + (size_t)r * NN * F;

        float part[8];
#pragma unroll
        for (int q = 0; q < 8; q++) part[q] = 0.f;

        int j = 0;
        // 8 edges per iteration: 4 per half
        for (; j + 8 <= cnt; j += 8) {
            int s[4];
#pragma unroll
            for (int q = 0; q < 4; q++) s[q] = __ldg(lst + j + half + 2 * q);
            uint4 w[4];
#pragma unroll
            for (int q = 0; q < 4; q++)
                w[q] = *reinterpret_cast<const uint4*>(tmp + (size_t)s[q] * F + c8);
#pragma unroll
            for (int q = 0; q < 4; q++) {
#pragma unroll
                for (int hpos = 0; hpos < 4; hpos++) {
                    uint32_t u = (&w[q].x)[hpos];
                    float2 f = __half22float2(*reinterpret_cast<__half2*>(&u));
                    part[hpos * 2]     += f.x;
                    part[hpos * 2 + 1] += f.y;
                }
            }
        }
        // tail: 2 edges per iteration (1 per half), predicated
        for (; j < cnt; j += 2) {
            int e = j + half;
            if (e < cnt) {
                int s = __ldg(lst + e);
                uint4 w = *reinterpret_cast<const uint4*>(tmp + (size_t)s * F + c8);
#pragma unroll
                for (int hpos = 0; hpos < 4; hpos++) {
                    uint32_t u = (&w.x)[hpos];
                    float2 f = __half22float2(*reinterpret_cast<__half2*>(&u));
                    part[hpos * 2]     += f.x;
                    part[hpos * 2 + 1] += f.y;
                }
            }
        }

        float nd = nds[r];
#pragma unroll
        for (int q = 0; q < 8; q++) acc[q] += part[q] * nd;
    }

    // cross-half reduce (lanes h and h+16 hold same columns, different edges)
#pragma unroll
    for (int q = 0; q < 8; q++)
        acc[q] += __shfl_xor_sync(0xFFFFFFFFu, acc[q], 16);

    if (half == 0) {
        float4 b0 = *reinterpret_cast<const float4*>(bias + c8);
        float4 b1 = *reinterpret_cast<const float4*>(bias + c8 + 4);
        float4 d0 = *reinterpret_cast<const float4*>(bias + F + c8);
        float4 d1 = *reinterpret_cast<const float4*>(bias + F + c8 + 4);
        float4 e0 = *reinterpret_cast<const float4*>(bias + 2 * F + c8);
        float4 e1 = *reinterpret_cast<const float4*>(bias + 2 * F + c8 + 4);
        acc[0] += b0.x + d0.x + e0.x; acc[1] += b0.y + d0.y + e0.y;
        acc[2] += b0.z + d0.z + e0.z; acc[3] += b0.w + d0.w + e0.w;
        acc[4] += b1.x + d1.x + e1.x; acc[5] += b1.y + d1.y + e1.y;
        acc[6] += b1.z + d1.z + e1.z; acc[7] += b1.w + d1.w + e1.w;

        if (relu) {
#pragma unroll
            for (int q = 0; q < 8; q++) acc[q] = fmaxf(acc[q], 0.f);
        }
        if (out_h) {
            __half2 h0 = __floats2half2_rn(acc[0], acc[1]);
            __half2 h1 = __floats2half2_rn(acc[2], acc[3]);
            __half2 h2 = __floats2half2_rn(acc[4], acc[5]);
            __half2 h3 = __floats2half2_rn(acc[6], acc[7]);
            *reinterpret_cast<uint4*>(out_h + (size_t)node * F + c8) =
                make_uint4(*reinterpret_cast<uint32_t*>(&h0),
                           *reinterpret_cast<uint32_t*>(&h1),
                           *reinterpret_cast<uint32_t*>(&h2),
                           *reinterpret_cast<uint32_t*>(&h3));
        } else {
            float* op = out_f + (size_t)node * F + c8;
            *reinterpret_cast<float4*>(op)     = make_float4(acc[0], acc[1], acc[2], acc[3]);
            *reinterpret_cast<float4*>(op + 4) = make_float4(acc[4], acc[5], acc[6], acc[7]);
        }
    }
}

// ---------------- launch ---------------------------------------------------
extern "C" void kernel_launch(void* const* d_in, const int* in_sizes, int n_in,
                              void* d_out, int out_size) {
    const float* x   = (const float*)d_in[0];
    const int*   src = (const int*)  d_in[1];
    const int*   dst = (const int*)  d_in[2];
    const float* W1  = (const float*)d_in[3];
    const float* b1  = (const float*)d_in[4];
    const float* W2  = (const float*)d_in[5];
    const float* b2  = (const float*)d_in[6];
    float* out = (float*)d_out;

    void* p;
    cudaGetSymbolAddress(&p, g_act);  __half* act = (__half*)p;
    cudaGetSymbolAddress(&p, g_tmp3); __half* tmp = (__half*)p;

    cudaFuncSetAttribute(gemm3_k,
                         cudaFuncAttributeMaxDynamicSharedMemorySize, GEMM_SMEM);

    const int T = 256;
    int gemm_blocks = (NN + BM - 1) / BM;      // 1563
    int agg_blocks  = (NN * 32 + T - 1) / T;   // warp per node
    int edge_blocks = (EE + T - 1) / T;

    // 0: W fp16 prep + zero norms
    prep_zero_k<<<(RR * NN + T - 1) / T, T>>>(W1, W2);
    // 1: degrees
    degree_k<<<dim3(edge_blocks, RR), T>>>(src, dst);
    // 2: src norms (all the GEMM needs)
    ns_fin_k<<<(RR * NN + T - 1) / T, T>>>();
    // 3: layer-1 GEMM  (profiled slot)
    gemm3_k<<<gemm_blocks, T, GEMM_SMEM>>>(x, nullptr, 0, tmp);
    // 4: scan (+fused chunk-total scan in tail block)
    scan_part_k<<<dim3(NB, RR), 1024>>>();
    // 5: dst norms + offsets + cursors
    nd_fin_k<<<(RR * NN + T - 1) / T, T>>>();
    // 6: CSR fill
    fill_csr_k<<<dim3(edge_blocks, RR), T>>>(src, dst);
    // 7: layer-1 aggregation (+bias+ReLU) -> fp16 activations
    agg_all_k<<<agg_blocks, T>>>(tmp, b1, act, nullptr, 1);
    // 8: layer-2 GEMM (fp16 activations in)
    gemm3_k<<<gemm_blocks, T, GEMM_SMEM>>>(nullptr, act, 1, tmp);
    // 9: layer-2 aggregation (+bias) -> fp32 output
    agg_all_k<<<agg_blocks, T>>>(tmp, b2, nullptr, out, 0);
}